// round 5
// baseline (speedup 1.0000x reference)
#include <cuda_runtime.h>

#define N_EMB   512
#define EMB_D   64
#define HWSZ    4096
#define NTOK    131072
#define TPB     256
#define TOKS_PER_CHUNK (TPB * 2)          // T=2 tokens per thread
#define NCHUNK  (NTOK / TOKS_PER_CHUNK)   // 256
#define GRID_A  148

// Output packing (float32, reference tuple order)
#define OFF_RES 0ULL
#define OFF_ARG 8388608ULL
#define OFF_W   8519680ULL
#define OFF_CS  8552448ULL
#define OFF_EA  8552960ULL

#define SMEM_BYTES ((N_EMB * EMB_D + N_EMB) * 4)   // 133120 B

__device__ float g_hist[N_EMB];
__device__ float g_esum[EMB_D * N_EMB];
__device__ float g_ww[N_EMB];
__device__ float g_wt[N_EMB * EMB_D];   // weight transposed: [j][d]
__device__ unsigned int g_work;
__device__ unsigned int g_done;

__device__ __forceinline__ unsigned long long ffma2(unsigned long long a,
                                                    unsigned long long b,
                                                    unsigned long long c) {
    unsigned long long d;
    asm("fma.rn.f32x2 %0, %1, %2, %3;" : "=l"(d) : "l"(a), "l"(b), "l"(c));
    return d;
}

__device__ __forceinline__ unsigned long long fadd2(unsigned long long a,
                                                    unsigned long long b) {
    unsigned long long d;
    asm("add.rn.f32x2 %0, %1, %2;" : "=l"(d) : "l"(a), "l"(b));
    return d;
}

__device__ __forceinline__ unsigned long long pack2(float lo, float hi) {
    unsigned long long r;
    asm("mov.b64 %0, {%1, %2};" : "=l"(r)
        : "r"(__float_as_uint(lo)), "r"(__float_as_uint(hi)));
    return r;
}

__device__ __forceinline__ void unpack2(unsigned long long v, float& lo, float& hi) {
    unsigned int a, b;
    asm("mov.b64 {%0, %1}, %2;" : "=r"(a), "=r"(b) : "l"(v));
    lo = __uint_as_float(a);
    hi = __uint_as_float(b);
}

// ---------------------------------------------------------------------------
// prep
// ---------------------------------------------------------------------------
__global__ void prep_kernel(const float* __restrict__ w) {
    int idx = blockIdx.x * blockDim.x + threadIdx.x;
    if (idx == 0) { g_work = 0u; g_done = 0u; }
    if (idx < EMB_D * N_EMB) {
        g_esum[idx] = 0.0f;
        int j = idx >> 6;
        int d = idx & 63;
        g_wt[idx] = w[d * N_EMB + j];
    }
    if (idx < N_EMB) {
        g_hist[idx] = 0.0f;
        float s = 0.0f;
        #pragma unroll
        for (int d = 0; d < EMB_D; d++) {
            float v = w[d * N_EMB + idx];
            s = __fadd_rn(s, __fmul_rn(v, v));
        }
        g_ww[idx] = s;
    }
}

// ---------------------------------------------------------------------------
// assign: persistent CTAs, T=2 tokens/thread, work-steal.
// q-loop software-pipelined with prefetch depth 2 so LDS.128 results arrive
// ~2 iterations (>29 cyc) before their FFMA2 consumers.
// ---------------------------------------------------------------------------
extern __shared__ float smem_dyn[];

__global__ void __launch_bounds__(TPB, 1)
assign_kernel(const float* __restrict__ x,
              const float* __restrict__ cs_in,
              const float* __restrict__ ea_in,
              float* __restrict__ out) {
    float* w_s  = smem_dyn;                     // [512][64] j-major
    float* ww_s = smem_dyn + N_EMB * EMB_D;     // [512]
    __shared__ int s_chunk;
    __shared__ unsigned int s_rank;

    int tid = threadIdx.x;

    // Stage transposed weight once per CTA: coalesced, conflict-free
    {
        const float4* src = (const float4*)g_wt;
        float4* dst = (float4*)w_s;
        #pragma unroll
        for (int i = 0; i < (N_EMB * EMB_D / 4) / TPB; i++)
            dst[i * TPB + tid] = src[i * TPB + tid];
        ww_s[tid]       = g_ww[tid];
        ww_s[tid + 256] = g_ww[tid + 256];
    }

    for (;;) {
        __syncthreads();
        if (tid == 0) s_chunk = (int)atomicAdd(&g_work, 1u);
        __syncthreads();
        int c = s_chunk;
        if (c >= NCHUNK) break;

        // chunk = 512 consecutive tokens, never crosses a batch (4096 | 512)
        int t0 = c * TOKS_PER_CHUNK + tid;     // token A
        int b0 = t0 >> 12;
        int hw0 = t0 & (HWSZ - 1);             // token B = hw0 + 256, same batch
        const float* xa_p = x + (size_t)b0 * EMB_D * HWSZ + hw0;

        // Both tokens' features -> packed f32x2 registers
        unsigned long long xpa[EMB_D / 2];
        unsigned long long xpb[EMB_D / 2];
        #pragma unroll
        for (int i = 0; i < EMB_D / 2; i++) {
            xpa[i] = pack2(xa_p[(2 * i) * HWSZ],       xa_p[(2 * i + 1) * HWSZ]);
            xpb[i] = pack2(xa_p[(2 * i) * HWSZ + 256], xa_p[(2 * i + 1) * HWSZ + 256]);
        }

        float bestA = 3.4e38f, bestB = 3.4e38f;
        int   biA = 0, biB = 0;

        #pragma unroll 1
        for (int j0 = 0; j0 < N_EMB; j0 += 2) {
            const ulonglong2* r0 = (const ulonglong2*)(w_s + (j0 + 0) * EMB_D);
            const ulonglong2* r1 = (const ulonglong2*)(w_s + (j0 + 1) * EMB_D);

            // accumulators: [codeword][token][even/odd half]
            unsigned long long a0Ae = 0ULL, a0Ao = 0ULL, a0Be = 0ULL, a0Bo = 0ULL;
            unsigned long long a1Ae = 0ULL, a1Ao = 0ULL, a1Be = 0ULL, a1Bo = 0ULL;

            // prefetch pipeline, depth 2
            ulonglong2 p0a = r0[0], p1a = r1[0];
            ulonglong2 p0b = r0[1], p1b = r1[1];

            #pragma unroll
            for (int qq = 0; qq < EMB_D / 8; qq++) {     // 8 double-steps
                // --- step q = 2qq ---
                ulonglong2 v0 = p0a, v1 = p1a;
                if (qq < EMB_D / 8 - 1) { p0a = r0[2 * qq + 2]; p1a = r1[2 * qq + 2]; }
                {
                    unsigned long long xaE = xpa[4 * qq],     xaO = xpa[4 * qq + 1];
                    unsigned long long xbE = xpb[4 * qq],     xbO = xpb[4 * qq + 1];
                    a0Ae = ffma2(xaE, v0.x, a0Ae);  a0Ao = ffma2(xaO, v0.y, a0Ao);
                    a0Be = ffma2(xbE, v0.x, a0Be);  a0Bo = ffma2(xbO, v0.y, a0Bo);
                    a1Ae = ffma2(xaE, v1.x, a1Ae);  a1Ao = ffma2(xaO, v1.y, a1Ao);
                    a1Be = ffma2(xbE, v1.x, a1Be);  a1Bo = ffma2(xbO, v1.y, a1Bo);
                }
                // --- step q = 2qq+1 ---
                ulonglong2 w0 = p0b, w1 = p1b;
                if (qq < EMB_D / 8 - 1) { p0b = r0[2 * qq + 3]; p1b = r1[2 * qq + 3]; }
                {
                    unsigned long long xaE = xpa[4 * qq + 2], xaO = xpa[4 * qq + 3];
                    unsigned long long xbE = xpb[4 * qq + 2], xbO = xpb[4 * qq + 3];
                    a0Ae = ffma2(xaE, w0.x, a0Ae);  a0Ao = ffma2(xaO, w0.y, a0Ao);
                    a0Be = ffma2(xbE, w0.x, a0Be);  a0Bo = ffma2(xbO, w0.y, a0Bo);
                    a1Ae = ffma2(xaE, w1.x, a1Ae);  a1Ao = ffma2(xaO, w1.y, a1Ao);
                    a1Be = ffma2(xbE, w1.x, a1Be);  a1Bo = ffma2(xbO, w1.y, a1Bo);
                }
            }

            float lo, hi;
            float q0 = ww_s[j0], q1 = ww_s[j0 + 1];
            unpack2(fadd2(a0Ae, a0Ao), lo, hi);
            float d0A = __fmaf_rn(-2.0f, __fadd_rn(lo, hi), q0);
            unpack2(fadd2(a1Ae, a1Ao), lo, hi);
            float d1A = __fmaf_rn(-2.0f, __fadd_rn(lo, hi), q1);
            unpack2(fadd2(a0Be, a0Bo), lo, hi);
            float d0B = __fmaf_rn(-2.0f, __fadd_rn(lo, hi), q0);
            unpack2(fadd2(a1Be, a1Bo), lo, hi);
            float d1B = __fmaf_rn(-2.0f, __fadd_rn(lo, hi), q1);

            // strict < ascending j => first-min tie-break (jnp.argmin)
            if (d0A < bestA) { bestA = d0A; biA = j0;     }
            if (d1A < bestA) { bestA = d1A; biA = j0 + 1; }
            if (d0B < bestB) { bestB = d0B; biB = j0;     }
            if (d1B < bestB) { bestB = d1B; biB = j0 + 1; }
        }

        out[OFF_ARG + (size_t)t0]       = (float)biA;
        out[OFF_ARG + (size_t)t0 + 256] = (float)biB;

        // quantized result from smem codebook (coalesced per d-plane)
        {
            float* ro = out + (size_t)b0 * EMB_D * HWSZ + hw0;
            const float4* wrowA = (const float4*)(w_s + biA * EMB_D);
            const float4* wrowB = (const float4*)(w_s + biB * EMB_D);
            #pragma unroll
            for (int i = 0; i < EMB_D / 4; i++) {
                float4 va = wrowA[i];
                float4 vb = wrowB[i];
                ro[(4 * i + 0) * HWSZ]       = va.x;
                ro[(4 * i + 1) * HWSZ]       = va.y;
                ro[(4 * i + 2) * HWSZ]       = va.z;
                ro[(4 * i + 3) * HWSZ]       = va.w;
                ro[(4 * i + 0) * HWSZ + 256] = vb.x;
                ro[(4 * i + 1) * HWSZ + 256] = vb.y;
                ro[(4 * i + 2) * HWSZ + 256] = vb.z;
                ro[(4 * i + 3) * HWSZ + 256] = vb.w;
            }
        }

        // EMA accumulators
        atomicAdd(&g_hist[biA], 1.0f);
        atomicAdd(&g_hist[biB], 1.0f);
        #pragma unroll
        for (int i = 0; i < EMB_D / 2; i++) {
            float lo, hi;
            unpack2(xpa[i], lo, hi);
            atomicAdd(&g_esum[(2 * i)     * N_EMB + biA], lo);
            atomicAdd(&g_esum[(2 * i + 1) * N_EMB + biA], hi);
            unpack2(xpb[i], lo, hi);
            atomicAdd(&g_esum[(2 * i)     * N_EMB + biB], lo);
            atomicAdd(&g_esum[(2 * i + 1) * N_EMB + biB], hi);
        }
    }

    // ------- merged finalize: last CTA to finish does the EMA update -------
    __threadfence();
    __syncthreads();
    if (tid == 0) s_rank = atomicAdd(&g_done, 1u);
    __syncthreads();
    if (s_rank == GRID_A - 1) {
        float* red = smem_dyn;

        const float DEC  = 0.99f;
        const float OMD  = (float)(1.0 - 0.99);
        const float EPSF = (float)1e-5;
        const float NEPS = (float)(N_EMB * 1e-5);

        float ncs0, ncs1;
        {
            float n0 = g_hist[tid];
            if (n0 == 0.0f) n0 = 1.0f;
            ncs0 = __fadd_rn(__fmul_rn(DEC, cs_in[tid]), __fmul_rn(OMD, n0));
            float n1 = g_hist[tid + 256];
            if (n1 == 0.0f) n1 = 1.0f;
            ncs1 = __fadd_rn(__fmul_rn(DEC, cs_in[tid + 256]), __fmul_rn(OMD, n1));
        }

        __syncthreads();
        red[tid] = ncs0 + ncs1;
        __syncthreads();
        #pragma unroll
        for (int s = 128; s > 0; s >>= 1) {
            if (tid < s) red[tid] += red[tid + s];
            __syncthreads();
        }
        float n = red[0];

        float csn0 = __fmul_rn(__fdiv_rn(__fadd_rn(ncs0, EPSF),
                                         __fadd_rn(n, NEPS)), n);
        float csn1 = __fmul_rn(__fdiv_rn(__fadd_rn(ncs1, EPSF),
                                         __fadd_rn(n, NEPS)), n);

        out[OFF_CS + tid]       = ncs0;
        out[OFF_CS + tid + 256] = ncs1;

        for (int d = 0; d < EMB_D; d++) {
            int i0 = d * N_EMB + tid;
            int i1 = i0 + 256;
            float e0 = __fadd_rn(__fmul_rn(DEC, ea_in[i0]),
                                 __fmul_rn(OMD, g_esum[i0]));
            float e1 = __fadd_rn(__fmul_rn(DEC, ea_in[i1]),
                                 __fmul_rn(OMD, g_esum[i1]));
            out[OFF_EA + i0] = e0;
            out[OFF_EA + i1] = e1;
            out[OFF_W  + i0] = __fdiv_rn(e0, csn0);
            out[OFF_W  + i1] = __fdiv_rn(e1, csn1);
        }
    }
}

// ---------------------------------------------------------------------------
extern "C" void kernel_launch(void* const* d_in, const int* in_sizes, int n_in,
                              void* d_out, int out_size) {
    const float* x  = (const float*)d_in[0];
    const float* w  = (const float*)d_in[1];
    const float* cs = (const float*)d_in[2];
    const float* ea = (const float*)d_in[3];
    float* out = (float*)d_out;

    cudaFuncSetAttribute(assign_kernel,
                         cudaFuncAttributeMaxDynamicSharedMemorySize, SMEM_BYTES);

    prep_kernel<<<128, 256>>>(w);
    assign_kernel<<<GRID_A, TPB, SMEM_BYTES>>>(x, cs, ea, out);
}